// round 1
// baseline (speedup 1.0000x reference)
#include <cuda_runtime.h>
#include <math.h>

#define S_LEN 2048
#define HDIM  4096
#define NHEADS 32
#define NKVH   8
#define HEADD  128
#define KVDIM  1024   // NKVH*HEADD

// ---------------- scratch (static device globals; no allocations) ----------
__device__ float g_q[S_LEN * HDIM];     // 32 MB
__device__ float g_k[S_LEN * KVDIM];    //  8 MB
__device__ float g_v[S_LEN * KVDIM];    //  8 MB
__device__ float g_o[S_LEN * HDIM];     // 32 MB
__device__ float g_cos[S_LEN * 64];
__device__ float g_sin[S_LEN * 64];

// ---------------------------------------------------------------------------
// C[M,N] = A[M,K] @ B[N,K]^T   (A,B row-major, K contiguous)
// M,N multiples of 128, K multiple of 8.
// ---------------------------------------------------------------------------
__global__ __launch_bounds__(256) void sgemm_nt(const float* __restrict__ A,
                                                const float* __restrict__ B,
                                                float* __restrict__ C,
                                                int M, int N, int K)
{
    const int BM = 128, BN = 128, BK = 8, TM = 8, TN = 8;
    __shared__ float As[BK][BM];
    __shared__ float Bs[BK][BN];

    const int tid = threadIdx.x;
    const int tx  = tid & 15;      // 0..15  (N direction)
    const int ty  = tid >> 4;      // 0..15  (M direction)

    const float* Ab = A + (size_t)blockIdx.y * BM * K;
    const float* Bb = B + (size_t)blockIdx.x * BN * K;

    const int lr = tid >> 1;           // 0..127 tile row
    const int lc = (tid & 1) * 4;      // 0 or 4 within BK

    float acc[TM][TN];
#pragma unroll
    for (int i = 0; i < TM; i++)
#pragma unroll
        for (int j = 0; j < TN; j++) acc[i][j] = 0.f;

    for (int k0 = 0; k0 < K; k0 += BK) {
        float4 av = *(const float4*)(Ab + (size_t)lr * K + k0 + lc);
        float4 bv = *(const float4*)(Bb + (size_t)lr * K + k0 + lc);
        __syncthreads();
        As[lc + 0][lr] = av.x; As[lc + 1][lr] = av.y;
        As[lc + 2][lr] = av.z; As[lc + 3][lr] = av.w;
        Bs[lc + 0][lr] = bv.x; Bs[lc + 1][lr] = bv.y;
        Bs[lc + 2][lr] = bv.z; Bs[lc + 3][lr] = bv.w;
        __syncthreads();
#pragma unroll
        for (int kk = 0; kk < BK; kk++) {
            float4 a0 = *(const float4*)&As[kk][ty * TM];
            float4 a1 = *(const float4*)&As[kk][ty * TM + 4];
            float4 b0 = *(const float4*)&Bs[kk][tx * TN];
            float4 b1 = *(const float4*)&Bs[kk][tx * TN + 4];
            float a[8] = {a0.x, a0.y, a0.z, a0.w, a1.x, a1.y, a1.z, a1.w};
            float b[8] = {b0.x, b0.y, b0.z, b0.w, b1.x, b1.y, b1.z, b1.w};
#pragma unroll
            for (int i = 0; i < TM; i++)
#pragma unroll
                for (int j = 0; j < TN; j++)
                    acc[i][j] += a[i] * b[j];
        }
    }

    float* Cb = C + (size_t)(blockIdx.y * BM + ty * TM) * N + blockIdx.x * BN + tx * TN;
#pragma unroll
    for (int i = 0; i < TM; i++) {
        *(float4*)(Cb + (size_t)i * N)     = make_float4(acc[i][0], acc[i][1], acc[i][2], acc[i][3]);
        *(float4*)(Cb + (size_t)i * N + 4) = make_float4(acc[i][4], acc[i][5], acc[i][6], acc[i][7]);
    }
}

// ---------------------------------------------------------------------------
// RoPE cos/sin table: g_cos/g_sin[s*64+i] for freq index i in [0,64)
// inv_freq_i = theta^(-i/64); computed in double, stored fp32 (matches fp32 ref
// within 1 ulp).
// ---------------------------------------------------------------------------
__global__ void rope_table()
{
    int idx = blockIdx.x * blockDim.x + threadIdx.x;
    if (idx >= S_LEN * 64) return;
    int s = idx >> 6, i = idx & 63;
    double inv = pow(500000.0, -(double)i / 64.0);
    double a = (double)s * inv;
    g_cos[idx] = (float)cos(a);
    g_sin[idx] = (float)sin(a);
}

// ---------------------------------------------------------------------------
// In-place RoPE on a [S, nheads*128] buffer.
// For freq index i: x0 = buf[i], x1 = buf[i+64]
//   new0 = x0*c - x1*s ; new1 = x1*c + x0*s
// ---------------------------------------------------------------------------
__global__ void rope_apply(float* __restrict__ buf, int nheads)
{
    int idx = blockIdx.x * blockDim.x + threadIdx.x;
    int total = S_LEN * nheads * 64;
    if (idx >= total) return;
    int i = idx & 63;
    int h = (idx >> 6) % nheads;
    int s = idx / (nheads * 64);
    float c  = g_cos[s * 64 + i];
    float sn = g_sin[s * 64 + i];
    float* p = buf + (size_t)s * nheads * HEADD + h * HEADD;
    float x0 = p[i];
    float x1 = p[i + 64];
    p[i]      = x0 * c - x1 * sn;
    p[i + 64] = x1 * c + x0 * sn;
}

// ---------------------------------------------------------------------------
// Flash attention (fp32, online softmax), causal, GQA (4 q-heads per kv-head).
// One block = 64 query rows of one head. 256 threads.
//   score phase: 16x16 thread grid, 4x4 micro-tiles
//   softmax/AV phase: 4 threads per row, 32 dims each
// smem strides padded (132 / 65) for conflict-free column reads.
// ---------------------------------------------------------------------------
#define FA_BM 64
#define FA_BN 64
#define TSTR  132
#define SSTR  65
#define FA_SMEM ((3 * FA_BM * TSTR + FA_BM * SSTR) * 4)

__global__ __launch_bounds__(256) void flash_attn(const float* __restrict__ Q,
                                                  const float* __restrict__ K,
                                                  const float* __restrict__ V,
                                                  float* __restrict__ O)
{
    extern __shared__ float sm[];
    float* Qs = sm;                       // [64][132]
    float* Ks = Qs + FA_BM * TSTR;        // [64][132]
    float* Vs = Ks + FA_BN * TSTR;        // [64][132]
    float* Ss = Vs + FA_BN * TSTR;        // [64][65]

    const int tid = threadIdx.x;
    const int h   = blockIdx.y;
    const int m0  = blockIdx.x * FA_BM;
    const int kvh = h >> 2;               // NH/NKV = 4

    for (int t = tid; t < FA_BM * HEADD; t += 256) {
        int r = t >> 7, d = t & 127;
        Qs[r * TSTR + d] = Q[(size_t)(m0 + r) * HDIM + h * HEADD + d];
    }

    const int row = tid >> 2;             // 0..63
    const int q4  = tid & 3;              // dim quarter (32 dims)
    float acc[32];
#pragma unroll
    for (int d = 0; d < 32; d++) acc[d] = 0.f;
    float m_i = -1e30f, l_i = 0.f;
    const float scale = 0.0883883476483184f;   // 1/sqrt(128)

    for (int j = 0; j <= blockIdx.x; j++) {
        const int n0 = j * FA_BN;
        __syncthreads();
        for (int t = tid; t < FA_BN * HEADD; t += 256) {
            int r = t >> 7, d = t & 127;
            Ks[r * TSTR + d] = K[(size_t)(n0 + r) * KVDIM + kvh * HEADD + d];
            Vs[r * TSTR + d] = V[(size_t)(n0 + r) * KVDIM + kvh * HEADD + d];
        }
        __syncthreads();

        // ---- scores: S = scale * Q K^T, causal mask on diagonal tile ----
        {
            const int tcx = tid & 15, tcy = tid >> 4;
            const int r0 = tcy * 4, c0 = tcx * 4;
            float s[4][4];
#pragma unroll
            for (int i = 0; i < 4; i++)
#pragma unroll
                for (int jj = 0; jj < 4; jj++) s[i][jj] = 0.f;

            for (int d = 0; d < HEADD; d += 4) {
                float4 qv[4], kv[4];
#pragma unroll
                for (int i = 0; i < 4; i++)
                    qv[i] = *(const float4*)&Qs[(r0 + i) * TSTR + d];
#pragma unroll
                for (int i = 0; i < 4; i++)
                    kv[i] = *(const float4*)&Ks[(c0 + i) * TSTR + d];
#pragma unroll
                for (int i = 0; i < 4; i++)
#pragma unroll
                    for (int jj = 0; jj < 4; jj++)
                        s[i][jj] += qv[i].x * kv[jj].x + qv[i].y * kv[jj].y
                                  + qv[i].z * kv[jj].z + qv[i].w * kv[jj].w;
            }
            const bool diag = (j == (int)blockIdx.x);
#pragma unroll
            for (int i = 0; i < 4; i++)
#pragma unroll
                for (int jj = 0; jj < 4; jj++) {
                    float val = s[i][jj] * scale;
                    if (diag && (n0 + c0 + jj > m0 + r0 + i)) val = -1e30f;
                    Ss[(r0 + i) * SSTR + c0 + jj] = val;
                }
        }
        __syncthreads();

        // ---- online softmax + P@V (4 lanes per row, within one warp) ----
        {
            float sv[16];
            float smax = -1e30f;
#pragma unroll
            for (int c = 0; c < 16; c++) {
                sv[c] = Ss[row * SSTR + q4 * 16 + c];
                smax = fmaxf(smax, sv[c]);
            }
            smax = fmaxf(smax, __shfl_xor_sync(0xffffffffu, smax, 1));
            smax = fmaxf(smax, __shfl_xor_sync(0xffffffffu, smax, 2));
            float m_new = fmaxf(m_i, smax);
            float corr  = __expf(m_i - m_new);
            float lsum  = 0.f;
#pragma unroll
            for (int c = 0; c < 16; c++) {
                float p = __expf(sv[c] - m_new);
                lsum += p;
                Ss[row * SSTR + q4 * 16 + c] = p;
            }
            lsum += __shfl_xor_sync(0xffffffffu, lsum, 1);
            lsum += __shfl_xor_sync(0xffffffffu, lsum, 2);
            m_i = m_new;
            l_i = l_i * corr + lsum;
#pragma unroll
            for (int d = 0; d < 32; d++) acc[d] *= corr;
            __syncwarp();

#pragma unroll 4
            for (int c = 0; c < FA_BN; c++) {
                float p = Ss[row * SSTR + c];
                const float4* vr = (const float4*)&Vs[c * TSTR + q4 * 32];
#pragma unroll
                for (int d4 = 0; d4 < 8; d4++) {
                    float4 vv = vr[d4];
                    acc[d4 * 4 + 0] += p * vv.x;
                    acc[d4 * 4 + 1] += p * vv.y;
                    acc[d4 * 4 + 2] += p * vv.z;
                    acc[d4 * 4 + 3] += p * vv.w;
                }
            }
        }
    }

    const float inv_l = 1.f / l_i;
    float* op = O + (size_t)(m0 + row) * HDIM + h * HEADD + q4 * 32;
#pragma unroll
    for (int d = 0; d < 32; d++) op[d] = acc[d] * inv_l;
}

// ---------------------------------------------------------------------------
extern "C" void kernel_launch(void* const* d_in, const int* in_sizes, int n_in,
                              void* d_out, int out_size)
{
    const float* x  = (const float*)d_in[0];
    const float* wq = (const float*)d_in[1];
    const float* wk = (const float*)d_in[2];
    const float* wv = (const float*)d_in[3];
    const float* wo = (const float*)d_in[4];
    float* out = (float*)d_out;

    float *qb, *kb, *vb, *ob;
    cudaGetSymbolAddress((void**)&qb, g_q);
    cudaGetSymbolAddress((void**)&kb, g_k);
    cudaGetSymbolAddress((void**)&vb, g_v);
    cudaGetSymbolAddress((void**)&ob, g_o);

    cudaFuncSetAttribute(flash_attn, cudaFuncAttributeMaxDynamicSharedMemorySize, FA_SMEM);

    // projections
    sgemm_nt<<<dim3(HDIM / 128,  S_LEN / 128), 256>>>(x, wq, qb, S_LEN, HDIM,  HDIM);
    sgemm_nt<<<dim3(KVDIM / 128, S_LEN / 128), 256>>>(x, wk, kb, S_LEN, KVDIM, HDIM);
    sgemm_nt<<<dim3(KVDIM / 128, S_LEN / 128), 256>>>(x, wv, vb, S_LEN, KVDIM, HDIM);

    // RoPE
    rope_table<<<(S_LEN * 64) / 256, 256>>>();
    rope_apply<<<(S_LEN * NHEADS * 64) / 256, 256>>>(qb, NHEADS);
    rope_apply<<<(S_LEN * NKVH * 64) / 256, 256>>>(kb, NKVH);

    // attention
    flash_attn<<<dim3(S_LEN / FA_BM, NHEADS), 256, FA_SMEM>>>(qb, kb, vb, ob);

    // output projection
    sgemm_nt<<<dim3(HDIM / 128, S_LEN / 128), 256>>>(ob, wo, out, S_LEN, HDIM, HDIM);
}

// round 3
// speedup vs baseline: 1.4028x; 1.4028x over previous
#include <cuda_runtime.h>
#include <cuda_bf16.h>
#include <cstdint>
#include <math.h>

#define S_LEN 2048
#define HDIM  4096
#define NHEADS 32
#define NKVH   8
#define HEADD  128
#define KVDIM  1024   // NKVH*HEADD

// ---------------- scratch (static device globals; no allocations) ----------
__device__ float g_q[S_LEN * HDIM];     // 32 MB
__device__ float g_k[S_LEN * KVDIM];    //  8 MB
__device__ float g_v[S_LEN * KVDIM];    //  8 MB
__device__ float g_o[S_LEN * HDIM];     // 32 MB
__device__ float g_cos[S_LEN * 64];
__device__ float g_sin[S_LEN * 64];

// ============================================================================
// helpers
// ============================================================================
__device__ __forceinline__ uint32_t smem_u32(const void* p) {
    uint32_t a;
    asm("{ .reg .u64 t; cvta.to.shared.u64 t, %1; cvt.u32.u64 %0, t; }"
        : "=r"(a) : "l"(p));
    return a;
}

__device__ __forceinline__ void ldmx4(uint32_t& r0, uint32_t& r1,
                                      uint32_t& r2, uint32_t& r3, uint32_t addr) {
    asm volatile("ldmatrix.sync.aligned.m8n8.x4.shared.b16 {%0,%1,%2,%3}, [%4];"
                 : "=r"(r0), "=r"(r1), "=r"(r2), "=r"(r3) : "r"(addr));
}

__device__ __forceinline__ void mma16816(float* c, const uint32_t* a, const uint32_t* b) {
    asm volatile(
        "mma.sync.aligned.m16n8k16.row.col.f32.bf16.bf16.f32 "
        "{%0,%1,%2,%3}, {%4,%5,%6,%7}, {%8,%9}, {%0,%1,%2,%3};"
        : "+f"(c[0]), "+f"(c[1]), "+f"(c[2]), "+f"(c[3])
        : "r"(a[0]), "r"(a[1]), "r"(a[2]), "r"(a[3]), "r"(b[0]), "r"(b[1]));
}

// split x -> (hi, lo) bf16, pack pairs
__device__ __forceinline__ void split2(float x, float y, uint32_t& hi, uint32_t& lo) {
    __nv_bfloat16 hx = __float2bfloat16_rn(x);
    __nv_bfloat16 hy = __float2bfloat16_rn(y);
    __nv_bfloat16 lx = __float2bfloat16_rn(x - __bfloat162float(hx));
    __nv_bfloat16 ly = __float2bfloat16_rn(y - __bfloat162float(hy));
    __nv_bfloat162 H = {hx, hy}, L = {lx, ly};
    hi = *reinterpret_cast<uint32_t*>(&H);
    lo = *reinterpret_cast<uint32_t*>(&L);
}

// ============================================================================
// bf16 split-precision tensor-core GEMM:  C[M,N] = A[M,K] @ B[N,K]^T
// BM=BN=128, BK=16, 256 threads (8 warps, each 32x64).
// 3 products: Ah*Bh + Ah*Bl + Al*Bh accumulated in fp32.
// ============================================================================
#define RSTR 48   // smem row stride in bytes (conflict-free for ldmatrix)

__global__ __launch_bounds__(256) void gemm_bf16s(const float* __restrict__ A,
                                                  const float* __restrict__ B,
                                                  float* __restrict__ C,
                                                  int M, int N, int K)
{
    __shared__ char sAh[128 * RSTR];
    __shared__ char sAl[128 * RSTR];
    __shared__ char sBh[128 * RSTR];
    __shared__ char sBl[128 * RSTR];

    const int tid  = threadIdx.x;
    const int wid  = tid >> 5;
    const int lane = tid & 31;
    const int wr   = wid >> 1;        // 0..3  (32-row group)
    const int wc   = wid & 1;         // 0..1  (64-col group)
    const int m0   = blockIdx.y * 128;
    const int n0   = blockIdx.x * 128;

    // loader mapping: 2 threads per row, 8 floats each
    const int lrow = tid >> 1;
    const int lhalf = tid & 1;
    const float* aptr = A + (size_t)(m0 + lrow) * K + lhalf * 8;
    const float* bptr = B + (size_t)(n0 + lrow) * K + lhalf * 8;

    const uint32_t sAh_b = smem_u32(sAh), sAl_b = smem_u32(sAl);
    const uint32_t sBh_b = smem_u32(sBh), sBl_b = smem_u32(sBl);
    const uint32_t stoff = (uint32_t)lrow * RSTR + lhalf * 16;

    // ldmatrix lane addresses
    // A (x4): rows m_base + (lane&15), koff = (lane>>4)*16
    const uint32_t a_row = (uint32_t)(wr * 32 + (lane & 15));
    const uint32_t a_koff = (uint32_t)((lane >> 4) * 16);
    // B (x4, two n-tiles): row = n_base + (lane&7) + ((lane>>4)&1)*8, koff = ((lane>>3)&1)*16
    const uint32_t b_row = (uint32_t)(wc * 64 + (lane & 7) + ((lane >> 4) & 1) * 8);
    const uint32_t b_koff = (uint32_t)(((lane >> 3) & 1) * 16);

    const uint32_t aAh = sAh_b + a_row * RSTR + a_koff;
    const uint32_t aAl = sAl_b + a_row * RSTR + a_koff;
    const uint32_t aBh = sBh_b + b_row * RSTR + b_koff;
    const uint32_t aBl = sBl_b + b_row * RSTR + b_koff;

    float acc[2][8][4];
#pragma unroll
    for (int mt = 0; mt < 2; mt++)
#pragma unroll
        for (int nt = 0; nt < 8; nt++)
#pragma unroll
            for (int i = 0; i < 4; i++) acc[mt][nt][i] = 0.f;

    float4 ra0 = ((const float4*)aptr)[0], ra1 = ((const float4*)aptr)[1];
    float4 rb0 = ((const float4*)bptr)[0], rb1 = ((const float4*)bptr)[1];

    const int NK = K >> 4;
    for (int it = 0; it < NK; ++it) {
        __syncthreads();   // prev ldmatrix reads finished
        {
            uint4 H, L;
            split2(ra0.x, ra0.y, H.x, L.x);
            split2(ra0.z, ra0.w, H.y, L.y);
            split2(ra1.x, ra1.y, H.z, L.z);
            split2(ra1.z, ra1.w, H.w, L.w);
            *(uint4*)(sAh + stoff) = H;
            *(uint4*)(sAl + stoff) = L;
            split2(rb0.x, rb0.y, H.x, L.x);
            split2(rb0.z, rb0.w, H.y, L.y);
            split2(rb1.x, rb1.y, H.z, L.z);
            split2(rb1.z, rb1.w, H.w, L.w);
            *(uint4*)(sBh + stoff) = H;
            *(uint4*)(sBl + stoff) = L;
        }
        __syncthreads();

        // fragments
        uint32_t Ah[2][4], Al[2][4], Bh[8][2], Bl[8][2];
#pragma unroll
        for (int mt = 0; mt < 2; mt++) {
            ldmx4(Ah[mt][0], Ah[mt][1], Ah[mt][2], Ah[mt][3], aAh + mt * 16 * RSTR);
            ldmx4(Al[mt][0], Al[mt][1], Al[mt][2], Al[mt][3], aAl + mt * 16 * RSTR);
        }
#pragma unroll
        for (int np = 0; np < 4; np++) {
            ldmx4(Bh[2*np][0], Bh[2*np][1], Bh[2*np+1][0], Bh[2*np+1][1],
                  aBh + np * 16 * RSTR);
            ldmx4(Bl[2*np][0], Bl[2*np][1], Bl[2*np+1][0], Bl[2*np+1][1],
                  aBl + np * 16 * RSTR);
        }

        // prefetch next chunk (overlaps MMA)
        if (it + 1 < NK) {
            const float* ap = aptr + (it + 1) * 16;
            const float* bp = bptr + (it + 1) * 16;
            ra0 = ((const float4*)ap)[0]; ra1 = ((const float4*)ap)[1];
            rb0 = ((const float4*)bp)[0]; rb1 = ((const float4*)bp)[1];
        }

#pragma unroll
        for (int mt = 0; mt < 2; mt++)
#pragma unroll
            for (int nt = 0; nt < 8; nt++) {
                mma16816(acc[mt][nt], Ah[mt], Bh[nt]);
                mma16816(acc[mt][nt], Ah[mt], Bl[nt]);
                mma16816(acc[mt][nt], Al[mt], Bh[nt]);
            }
    }

    // epilogue
    const int gid = lane >> 2, tig = lane & 3;
#pragma unroll
    for (int mt = 0; mt < 2; mt++) {
        const int row = m0 + wr * 32 + mt * 16 + gid;
#pragma unroll
        for (int nt = 0; nt < 8; nt++) {
            const int col = n0 + wc * 64 + nt * 8 + tig * 2;
            *(float2*)(C + (size_t)row * N + col) =
                make_float2(acc[mt][nt][0], acc[mt][nt][1]);
            *(float2*)(C + (size_t)(row + 8) * N + col) =
                make_float2(acc[mt][nt][2], acc[mt][nt][3]);
        }
    }
}

// ---------------------------------------------------------------------------
// RoPE table + apply (unchanged)
// ---------------------------------------------------------------------------
__global__ void rope_table()
{
    int idx = blockIdx.x * blockDim.x + threadIdx.x;
    if (idx >= S_LEN * 64) return;
    int s = idx >> 6, i = idx & 63;
    double inv = pow(500000.0, -(double)i / 64.0);
    double a = (double)s * inv;
    g_cos[idx] = (float)cos(a);
    g_sin[idx] = (float)sin(a);
}

__global__ void rope_apply(float* __restrict__ buf, int nheads)
{
    int idx = blockIdx.x * blockDim.x + threadIdx.x;
    int total = S_LEN * nheads * 64;
    if (idx >= total) return;
    int i = idx & 63;
    int h = (idx >> 6) % nheads;
    int s = idx / (nheads * 64);
    float c  = g_cos[s * 64 + i];
    float sn = g_sin[s * 64 + i];
    float* p = buf + (size_t)s * nheads * HEADD + h * HEADD;
    float x0 = p[i];
    float x1 = p[i + 64];
    p[i]      = x0 * c - x1 * sn;
    p[i + 64] = x1 * c + x0 * sn;
}

// ---------------------------------------------------------------------------
// Flash attention (fp32, online softmax), causal, GQA — unchanged from R1.
// ---------------------------------------------------------------------------
#define FA_BM 64
#define FA_BN 64
#define TSTR  132
#define SSTR  65
#define FA_SMEM ((3 * FA_BM * TSTR + FA_BM * SSTR) * 4)

__global__ __launch_bounds__(256) void flash_attn(const float* __restrict__ Q,
                                                  const float* __restrict__ K,
                                                  const float* __restrict__ V,
                                                  float* __restrict__ O)
{
    extern __shared__ float smf[];
    float* Qs = smf;
    float* Ks = Qs + FA_BM * TSTR;
    float* Vs = Ks + FA_BN * TSTR;
    float* Ss = Vs + FA_BN * TSTR;

    const int tid = threadIdx.x;
    const int h   = blockIdx.y;
    const int m0  = blockIdx.x * FA_BM;
    const int kvh = h >> 2;

    for (int t = tid; t < FA_BM * HEADD; t += 256) {
        int r = t >> 7, d = t & 127;
        Qs[r * TSTR + d] = Q[(size_t)(m0 + r) * HDIM + h * HEADD + d];
    }

    const int row = tid >> 2;
    const int q4  = tid & 3;
    float acc[32];
#pragma unroll
    for (int d = 0; d < 32; d++) acc[d] = 0.f;
    float m_i = -1e30f, l_i = 0.f;
    const float scale = 0.0883883476483184f;

    for (int j = 0; j <= blockIdx.x; j++) {
        const int n0 = j * FA_BN;
        __syncthreads();
        for (int t = tid; t < FA_BN * HEADD; t += 256) {
            int r = t >> 7, d = t & 127;
            Ks[r * TSTR + d] = K[(size_t)(n0 + r) * KVDIM + kvh * HEADD + d];
            Vs[r * TSTR + d] = V[(size_t)(n0 + r) * KVDIM + kvh * HEADD + d];
        }
        __syncthreads();

        {
            const int tcx = tid & 15, tcy = tid >> 4;
            const int r0 = tcy * 4, c0 = tcx * 4;
            float s[4][4];
#pragma unroll
            for (int i = 0; i < 4; i++)
#pragma unroll
                for (int jj = 0; jj < 4; jj++) s[i][jj] = 0.f;

            for (int d = 0; d < HEADD; d += 4) {
                float4 qv[4], kv[4];
#pragma unroll
                for (int i = 0; i < 4; i++)
                    qv[i] = *(const float4*)&Qs[(r0 + i) * TSTR + d];
#pragma unroll
                for (int i = 0; i < 4; i++)
                    kv[i] = *(const float4*)&Ks[(c0 + i) * TSTR + d];
#pragma unroll
                for (int i = 0; i < 4; i++)
#pragma unroll
                    for (int jj = 0; jj < 4; jj++)
                        s[i][jj] += qv[i].x * kv[jj].x + qv[i].y * kv[jj].y
                                  + qv[i].z * kv[jj].z + qv[i].w * kv[jj].w;
            }
            const bool diag = (j == (int)blockIdx.x);
#pragma unroll
            for (int i = 0; i < 4; i++)
#pragma unroll
                for (int jj = 0; jj < 4; jj++) {
                    float val = s[i][jj] * scale;
                    if (diag && (n0 + c0 + jj > m0 + r0 + i)) val = -1e30f;
                    Ss[(r0 + i) * SSTR + c0 + jj] = val;
                }
        }
        __syncthreads();

        {
            float sv[16];
            float smax = -1e30f;
#pragma unroll
            for (int c = 0; c < 16; c++) {
                sv[c] = Ss[row * SSTR + q4 * 16 + c];
                smax = fmaxf(smax, sv[c]);
            }
            smax = fmaxf(smax, __shfl_xor_sync(0xffffffffu, smax, 1));
            smax = fmaxf(smax, __shfl_xor_sync(0xffffffffu, smax, 2));
            float m_new = fmaxf(m_i, smax);
            float corr  = __expf(m_i - m_new);
            float lsum  = 0.f;
#pragma unroll
            for (int c = 0; c < 16; c++) {
                float p = __expf(sv[c] - m_new);
                lsum += p;
                Ss[row * SSTR + q4 * 16 + c] = p;
            }
            lsum += __shfl_xor_sync(0xffffffffu, lsum, 1);
            lsum += __shfl_xor_sync(0xffffffffu, lsum, 2);
            m_i = m_new;
            l_i = l_i * corr + lsum;
#pragma unroll
            for (int d = 0; d < 32; d++) acc[d] *= corr;
            __syncwarp();

#pragma unroll 4
            for (int c = 0; c < FA_BN; c++) {
                float p = Ss[row * SSTR + c];
                const float4* vr = (const float4*)&Vs[c * TSTR + q4 * 32];
#pragma unroll
                for (int d4 = 0; d4 < 8; d4++) {
                    float4 vv = vr[d4];
                    acc[d4 * 4 + 0] += p * vv.x;
                    acc[d4 * 4 + 1] += p * vv.y;
                    acc[d4 * 4 + 2] += p * vv.z;
                    acc[d4 * 4 + 3] += p * vv.w;
                }
            }
        }
    }

    const float inv_l = 1.f / l_i;
    float* op = O + (size_t)(m0 + row) * HDIM + h * HEADD + q4 * 32;
#pragma unroll
    for (int d = 0; d < 32; d++) op[d] = acc[d] * inv_l;
}

// ---------------------------------------------------------------------------
extern "C" void kernel_launch(void* const* d_in, const int* in_sizes, int n_in,
                              void* d_out, int out_size)
{
    const float* x  = (const float*)d_in[0];
    const float* wq = (const float*)d_in[1];
    const float* wk = (const float*)d_in[2];
    const float* wv = (const float*)d_in[3];
    const float* wo = (const float*)d_in[4];
    float* out = (float*)d_out;

    float *qb, *kb, *vb, *ob;
    cudaGetSymbolAddress((void**)&qb, g_q);
    cudaGetSymbolAddress((void**)&kb, g_k);
    cudaGetSymbolAddress((void**)&vb, g_v);
    cudaGetSymbolAddress((void**)&ob, g_o);

    cudaFuncSetAttribute(flash_attn, cudaFuncAttributeMaxDynamicSharedMemorySize, FA_SMEM);

    // projections (bf16 split-precision tensor-core)
    gemm_bf16s<<<dim3(HDIM / 128,  S_LEN / 128), 256>>>(x, wq, qb, S_LEN, HDIM,  HDIM);
    gemm_bf16s<<<dim3(KVDIM / 128, S_LEN / 128), 256>>>(x, wk, kb, S_LEN, KVDIM, HDIM);
    gemm_bf16s<<<dim3(KVDIM / 128, S_LEN / 128), 256>>>(x, wv, vb, S_LEN, KVDIM, HDIM);

    // RoPE
    rope_table<<<(S_LEN * 64) / 256, 256>>>();
    rope_apply<<<(S_LEN * NHEADS * 64) / 256, 256>>>(qb, NHEADS);
    rope_apply<<<(S_LEN * NKVH * 64) / 256, 256>>>(kb, NKVH);

    // attention
    flash_attn<<<dim3(S_LEN / FA_BM, NHEADS), 256, FA_SMEM>>>(qb, kb, vb, ob);

    // output projection
    gemm_bf16s<<<dim3(HDIM / 128, S_LEN / 128), 256>>>(ob, wo, out, S_LEN, HDIM, HDIM);
}

// round 4
// speedup vs baseline: 4.3060x; 3.0694x over previous
#include <cuda_runtime.h>
#include <cuda_bf16.h>
#include <cstdint>
#include <math.h>

#define S_LEN 2048
#define HDIM  4096
#define NHEADS 32
#define NKVH   8
#define HEADD  128
#define KVDIM  1024   // NKVH*HEADD

// ---------------- scratch (static device globals; no allocations) ----------
__device__ float g_q[S_LEN * HDIM];     // 32 MB
__device__ float g_k[S_LEN * KVDIM];    //  8 MB
__device__ float g_v[S_LEN * KVDIM];    //  8 MB
__device__ float g_o[S_LEN * HDIM];     // 32 MB
__device__ float g_cos[S_LEN * 64];
__device__ float g_sin[S_LEN * 64];

// ============================================================================
// helpers
// ============================================================================
__device__ __forceinline__ uint32_t smem_u32(const void* p) {
    uint32_t a;
    asm("{ .reg .u64 t; cvta.to.shared.u64 t, %1; cvt.u32.u64 %0, t; }"
        : "=r"(a) : "l"(p));
    return a;
}

__device__ __forceinline__ void ldmx4(uint32_t& r0, uint32_t& r1,
                                      uint32_t& r2, uint32_t& r3, uint32_t addr) {
    asm volatile("ldmatrix.sync.aligned.m8n8.x4.shared.b16 {%0,%1,%2,%3}, [%4];"
                 : "=r"(r0), "=r"(r1), "=r"(r2), "=r"(r3) : "r"(addr));
}
__device__ __forceinline__ void ldmx4t(uint32_t& r0, uint32_t& r1,
                                       uint32_t& r2, uint32_t& r3, uint32_t addr) {
    asm volatile("ldmatrix.sync.aligned.m8n8.x4.trans.shared.b16 {%0,%1,%2,%3}, [%4];"
                 : "=r"(r0), "=r"(r1), "=r"(r2), "=r"(r3) : "r"(addr));
}

__device__ __forceinline__ void mma16816(float* c, const uint32_t* a, const uint32_t* b) {
    asm volatile(
        "mma.sync.aligned.m16n8k16.row.col.f32.bf16.bf16.f32 "
        "{%0,%1,%2,%3}, {%4,%5,%6,%7}, {%8,%9}, {%0,%1,%2,%3};"
        : "+f"(c[0]), "+f"(c[1]), "+f"(c[2]), "+f"(c[3])
        : "r"(a[0]), "r"(a[1]), "r"(a[2]), "r"(a[3]), "r"(b[0]), "r"(b[1]));
}

__device__ __forceinline__ float ex2(float x) {
    float r;
    asm("ex2.approx.ftz.f32 %0, %1;" : "=f"(r) : "f"(x));
    return r;
}

// split x -> (hi, lo) bf16, pack pairs
__device__ __forceinline__ void split2(float x, float y, uint32_t& hi, uint32_t& lo) {
    __nv_bfloat16 hx = __float2bfloat16_rn(x);
    __nv_bfloat16 hy = __float2bfloat16_rn(y);
    __nv_bfloat16 lx = __float2bfloat16_rn(x - __bfloat162float(hx));
    __nv_bfloat16 ly = __float2bfloat16_rn(y - __bfloat162float(hy));
    __nv_bfloat162 H = {hx, hy}, L = {lx, ly};
    hi = *reinterpret_cast<uint32_t*>(&H);
    lo = *reinterpret_cast<uint32_t*>(&L);
}

// ============================================================================
// bf16 split-precision tensor-core GEMM:  C[M,N] = A[M,K] @ B[N,K]^T
// (unchanged from round 3 — validated)
// ============================================================================
#define RSTR 48

__global__ __launch_bounds__(256) void gemm_bf16s(const float* __restrict__ A,
                                                  const float* __restrict__ B,
                                                  float* __restrict__ C,
                                                  int M, int N, int K)
{
    __shared__ char sAh[128 * RSTR];
    __shared__ char sAl[128 * RSTR];
    __shared__ char sBh[128 * RSTR];
    __shared__ char sBl[128 * RSTR];

    const int tid  = threadIdx.x;
    const int wid  = tid >> 5;
    const int lane = tid & 31;
    const int wr   = wid >> 1;
    const int wc   = wid & 1;
    const int m0   = blockIdx.y * 128;
    const int n0   = blockIdx.x * 128;

    const int lrow = tid >> 1;
    const int lhalf = tid & 1;
    const float* aptr = A + (size_t)(m0 + lrow) * K + lhalf * 8;
    const float* bptr = B + (size_t)(n0 + lrow) * K + lhalf * 8;

    const uint32_t sAh_b = smem_u32(sAh), sAl_b = smem_u32(sAl);
    const uint32_t sBh_b = smem_u32(sBh), sBl_b = smem_u32(sBl);
    const uint32_t stoff = (uint32_t)lrow * RSTR + lhalf * 16;

    const uint32_t a_row = (uint32_t)(wr * 32 + (lane & 15));
    const uint32_t a_koff = (uint32_t)((lane >> 4) * 16);
    const uint32_t b_row = (uint32_t)(wc * 64 + (lane & 7) + ((lane >> 4) & 1) * 8);
    const uint32_t b_koff = (uint32_t)(((lane >> 3) & 1) * 16);

    const uint32_t aAh = sAh_b + a_row * RSTR + a_koff;
    const uint32_t aAl = sAl_b + a_row * RSTR + a_koff;
    const uint32_t aBh = sBh_b + b_row * RSTR + b_koff;
    const uint32_t aBl = sBl_b + b_row * RSTR + b_koff;

    float acc[2][8][4];
#pragma unroll
    for (int mt = 0; mt < 2; mt++)
#pragma unroll
        for (int nt = 0; nt < 8; nt++)
#pragma unroll
            for (int i = 0; i < 4; i++) acc[mt][nt][i] = 0.f;

    float4 ra0 = ((const float4*)aptr)[0], ra1 = ((const float4*)aptr)[1];
    float4 rb0 = ((const float4*)bptr)[0], rb1 = ((const float4*)bptr)[1];

    const int NK = K >> 4;
    for (int it = 0; it < NK; ++it) {
        __syncthreads();
        {
            uint4 H, L;
            split2(ra0.x, ra0.y, H.x, L.x);
            split2(ra0.z, ra0.w, H.y, L.y);
            split2(ra1.x, ra1.y, H.z, L.z);
            split2(ra1.z, ra1.w, H.w, L.w);
            *(uint4*)(sAh + stoff) = H;
            *(uint4*)(sAl + stoff) = L;
            split2(rb0.x, rb0.y, H.x, L.x);
            split2(rb0.z, rb0.w, H.y, L.y);
            split2(rb1.x, rb1.y, H.z, L.z);
            split2(rb1.z, rb1.w, H.w, L.w);
            *(uint4*)(sBh + stoff) = H;
            *(uint4*)(sBl + stoff) = L;
        }
        __syncthreads();

        uint32_t Ah[2][4], Al[2][4], Bh[8][2], Bl[8][2];
#pragma unroll
        for (int mt = 0; mt < 2; mt++) {
            ldmx4(Ah[mt][0], Ah[mt][1], Ah[mt][2], Ah[mt][3], aAh + mt * 16 * RSTR);
            ldmx4(Al[mt][0], Al[mt][1], Al[mt][2], Al[mt][3], aAl + mt * 16 * RSTR);
        }
#pragma unroll
        for (int np = 0; np < 4; np++) {
            ldmx4(Bh[2*np][0], Bh[2*np][1], Bh[2*np+1][0], Bh[2*np+1][1],
                  aBh + np * 16 * RSTR);
            ldmx4(Bl[2*np][0], Bl[2*np][1], Bl[2*np+1][0], Bl[2*np+1][1],
                  aBl + np * 16 * RSTR);
        }

        if (it + 1 < NK) {
            const float* ap = aptr + (it + 1) * 16;
            const float* bp = bptr + (it + 1) * 16;
            ra0 = ((const float4*)ap)[0]; ra1 = ((const float4*)ap)[1];
            rb0 = ((const float4*)bp)[0]; rb1 = ((const float4*)bp)[1];
        }

#pragma unroll
        for (int mt = 0; mt < 2; mt++)
#pragma unroll
            for (int nt = 0; nt < 8; nt++) {
                mma16816(acc[mt][nt], Ah[mt], Bh[nt]);
                mma16816(acc[mt][nt], Ah[mt], Bl[nt]);
                mma16816(acc[mt][nt], Al[mt], Bh[nt]);
            }
    }

    const int gid = lane >> 2, tig = lane & 3;
#pragma unroll
    for (int mt = 0; mt < 2; mt++) {
        const int row = m0 + wr * 32 + mt * 16 + gid;
#pragma unroll
        for (int nt = 0; nt < 8; nt++) {
            const int col = n0 + wc * 64 + nt * 8 + tig * 2;
            *(float2*)(C + (size_t)row * N + col) =
                make_float2(acc[mt][nt][0], acc[mt][nt][1]);
            *(float2*)(C + (size_t)(row + 8) * N + col) =
                make_float2(acc[mt][nt][2], acc[mt][nt][3]);
        }
    }
}

// ---------------------------------------------------------------------------
// RoPE table + apply (unchanged)
// ---------------------------------------------------------------------------
__global__ void rope_table()
{
    int idx = blockIdx.x * blockDim.x + threadIdx.x;
    if (idx >= S_LEN * 64) return;
    int s = idx >> 6, i = idx & 63;
    double inv = pow(500000.0, -(double)i / 64.0);
    double a = (double)s * inv;
    g_cos[idx] = (float)cos(a);
    g_sin[idx] = (float)sin(a);
}

__global__ void rope_apply(float* __restrict__ buf, int nheads)
{
    int idx = blockIdx.x * blockDim.x + threadIdx.x;
    int total = S_LEN * nheads * 64;
    if (idx >= total) return;
    int i = idx & 63;
    int h = (idx >> 6) % nheads;
    int s = idx / (nheads * 64);
    float c  = g_cos[s * 64 + i];
    float sn = g_sin[s * 64 + i];
    float* p = buf + (size_t)s * nheads * HEADD + h * HEADD;
    float x0 = p[i];
    float x1 = p[i + 64];
    p[i]      = x0 * c - x1 * sn;
    p[i + 64] = x1 * c + x0 * sn;
}

// ============================================================================
// Tensor-core flash attention (bf16 split, fp32 accum), causal, GQA.
// BM=128 (8 warps x 16 rows), BN=64. smem: Q/K/V as bf16 hi+lo, 272B stride.
// Softmax in log2 domain (scale*log2e folded into Q), ex2.approx MUFU.
// ============================================================================
#define FRS 272
#define FQH 0
#define FQL (128 * FRS)
#define FKH (2 * 128 * FRS)
#define FKL (FKH + 64 * FRS)
#define FVH (FKH + 2 * 64 * FRS)
#define FVL (FKH + 3 * 64 * FRS)
#define FA2_SMEM (FKH + 4 * 64 * FRS)   // 139264 bytes

__global__ __launch_bounds__(256) void flash_mma(const float* __restrict__ Q,
                                                 const float* __restrict__ K,
                                                 const float* __restrict__ V,
                                                 float* __restrict__ O)
{
    extern __shared__ char sm[];
    const uint32_t sb = smem_u32(sm);
    const int tid = threadIdx.x, lane = tid & 31, wid = tid >> 5;
    const int h = blockIdx.y;
    const int m0 = blockIdx.x * 128;
    const int kvh = h >> 2;
    // (1/sqrt(128)) * log2(e)
    const float qscale = 0.0883883476483184f * 1.4426950408889634f;

    // ---- load Q (scaled) ----
    {
        int row = tid >> 1, half = tid & 1;
        const float* qp = Q + (size_t)(m0 + row) * HDIM + h * HEADD + half * 64;
        char* dh = sm + FQH + row * FRS + half * 128;
        char* dl = sm + FQL + row * FRS + half * 128;
#pragma unroll
        for (int c = 0; c < 16; c++) {
            float4 v = ((const float4*)qp)[c];
            v.x *= qscale; v.y *= qscale; v.z *= qscale; v.w *= qscale;
            uint32_t h0, l0, h1, l1;
            split2(v.x, v.y, h0, l0);
            split2(v.z, v.w, h1, l1);
            ((uint2*)dh)[c] = make_uint2(h0, h1);
            ((uint2*)dl)[c] = make_uint2(l0, l1);
        }
    }

    float o[16][4];
#pragma unroll
    for (int dt = 0; dt < 16; dt++)
#pragma unroll
        for (int i = 0; i < 4; i++) o[dt][i] = 0.f;
    float mA = -1e30f, mB = -1e30f, lA = 0.f, lB = 0.f;

    const int wrow0 = m0 + wid * 16;

    // ldmatrix lane addresses
    const uint32_t aQh = sb + FQH + (wid * 16 + (lane & 15)) * FRS + ((lane >> 4) & 1) * 16;
    const uint32_t aQl = aQh + (FQL - FQH);
    const uint32_t kRow = (uint32_t)((lane & 7) + ((lane >> 4) & 1) * 8);
    const uint32_t kKo  = (uint32_t)(((lane >> 3) & 1) * 16);
    const uint32_t aKh = sb + FKH + kRow * FRS + kKo;
    const uint32_t aKl = aKh + (FKL - FKH);
    const uint32_t vRow = (uint32_t)((lane & 7) + ((lane >> 3) & 1) * 8);
    const uint32_t vDo  = (uint32_t)(((lane >> 4) & 1) * 16);
    const uint32_t aVh = sb + FVH + vRow * FRS + vDo;
    const uint32_t aVl = aVh + (FVL - FVH);

    const int jmax = 2 * blockIdx.x + 1;
    for (int j = 0; j <= jmax; j++) {
        const int n0 = j * 64;
        __syncthreads();
        // ---- load K/V tile ----
        {
            int row = tid >> 2, q = tid & 3;
            const float* kp = K + (size_t)(n0 + row) * KVDIM + kvh * HEADD + q * 32;
            const float* vp = V + (size_t)(n0 + row) * KVDIM + kvh * HEADD + q * 32;
            char* kh = sm + FKH + row * FRS + q * 64;
            char* kl = sm + FKL + row * FRS + q * 64;
            char* vh = sm + FVH + row * FRS + q * 64;
            char* vl = sm + FVL + row * FRS + q * 64;
#pragma unroll
            for (int c = 0; c < 8; c++) {
                float4 x = ((const float4*)kp)[c];
                uint32_t h0, l0, h1, l1;
                split2(x.x, x.y, h0, l0);
                split2(x.z, x.w, h1, l1);
                ((uint2*)kh)[c] = make_uint2(h0, h1);
                ((uint2*)kl)[c] = make_uint2(l0, l1);
                x = ((const float4*)vp)[c];
                split2(x.x, x.y, h0, l0);
                split2(x.z, x.w, h1, l1);
                ((uint2*)vh)[c] = make_uint2(h0, h1);
                ((uint2*)vl)[c] = make_uint2(l0, l1);
            }
        }
        __syncthreads();

        if (n0 > wrow0 + 15) continue;   // fully masked for this warp

        // ---- scores: S = Qs . Ks^T (3-product split) ----
        float s[8][4];
#pragma unroll
        for (int t = 0; t < 8; t++)
#pragma unroll
            for (int i = 0; i < 4; i++) s[t][i] = 0.f;

#pragma unroll
        for (int kc = 0; kc < 8; kc++) {
            uint32_t qh[4], ql[4];
            ldmx4(qh[0], qh[1], qh[2], qh[3], aQh + kc * 32);
            ldmx4(ql[0], ql[1], ql[2], ql[3], aQl + kc * 32);
#pragma unroll
            for (int np = 0; np < 4; np++) {
                uint32_t kh[4], kl[4];
                ldmx4(kh[0], kh[1], kh[2], kh[3], aKh + np * 16 * FRS + kc * 32);
                ldmx4(kl[0], kl[1], kl[2], kl[3], aKl + np * 16 * FRS + kc * 32);
                mma16816(s[2*np],   qh, kh);
                mma16816(s[2*np],   qh, kl);
                mma16816(s[2*np],   ql, kh);
                mma16816(s[2*np+1], qh, kh + 2);
                mma16816(s[2*np+1], qh, kl + 2);
                mma16816(s[2*np+1], ql, kh + 2);
            }
        }

        // ---- causal mask ----
        const int rA = wrow0 + (lane >> 2);
        const int rB = rA + 8;
        const int cb = n0 + 2 * (lane & 3);
        if (n0 + 63 > wrow0) {
#pragma unroll
            for (int t = 0; t < 8; t++) {
                int c0 = cb + 8 * t;
                if (c0     > rA) s[t][0] = -1e30f;
                if (c0 + 1 > rA) s[t][1] = -1e30f;
                if (c0     > rB) s[t][2] = -1e30f;
                if (c0 + 1 > rB) s[t][3] = -1e30f;
            }
        }

        // ---- online softmax (log2 domain) ----
        float xA = -1e30f, xB = -1e30f;
#pragma unroll
        for (int t = 0; t < 8; t++) {
            xA = fmaxf(xA, fmaxf(s[t][0], s[t][1]));
            xB = fmaxf(xB, fmaxf(s[t][2], s[t][3]));
        }
        xA = fmaxf(xA, __shfl_xor_sync(0xffffffffu, xA, 1));
        xA = fmaxf(xA, __shfl_xor_sync(0xffffffffu, xA, 2));
        xB = fmaxf(xB, __shfl_xor_sync(0xffffffffu, xB, 1));
        xB = fmaxf(xB, __shfl_xor_sync(0xffffffffu, xB, 2));
        float mAn = fmaxf(mA, xA), mBn = fmaxf(mB, xB);
        float cA = ex2(mA - mAn), cB = ex2(mB - mBn);
        mA = mAn; mB = mBn;
        float sumA = 0.f, sumB = 0.f;
#pragma unroll
        for (int t = 0; t < 8; t++) {
            s[t][0] = ex2(s[t][0] - mA); sumA += s[t][0];
            s[t][1] = ex2(s[t][1] - mA); sumA += s[t][1];
            s[t][2] = ex2(s[t][2] - mB); sumB += s[t][2];
            s[t][3] = ex2(s[t][3] - mB); sumB += s[t][3];
        }
        sumA += __shfl_xor_sync(0xffffffffu, sumA, 1);
        sumA += __shfl_xor_sync(0xffffffffu, sumA, 2);
        sumB += __shfl_xor_sync(0xffffffffu, sumB, 1);
        sumB += __shfl_xor_sync(0xffffffffu, sumB, 2);
        lA = lA * cA + sumA;
        lB = lB * cB + sumB;
#pragma unroll
        for (int dt = 0; dt < 16; dt++) {
            o[dt][0] *= cA; o[dt][1] *= cA;
            o[dt][2] *= cB; o[dt][3] *= cB;
        }

        // ---- O += P @ V (3-product split) ----
#pragma unroll
        for (int kc = 0; kc < 4; kc++) {
            uint32_t ph[4], pl[4];
            split2(s[2*kc][0],   s[2*kc][1],   ph[0], pl[0]);
            split2(s[2*kc][2],   s[2*kc][3],   ph[1], pl[1]);
            split2(s[2*kc+1][0], s[2*kc+1][1], ph[2], pl[2]);
            split2(s[2*kc+1][2], s[2*kc+1][3], ph[3], pl[3]);
#pragma unroll
            for (int dp = 0; dp < 8; dp++) {
                uint32_t vh[4], vl[4];
                ldmx4t(vh[0], vh[1], vh[2], vh[3], aVh + kc * 16 * FRS + dp * 32);
                ldmx4t(vl[0], vl[1], vl[2], vl[3], aVl + kc * 16 * FRS + dp * 32);
                mma16816(o[2*dp],   ph, vh);
                mma16816(o[2*dp],   ph, vl);
                mma16816(o[2*dp],   pl, vh);
                mma16816(o[2*dp+1], ph, vh + 2);
                mma16816(o[2*dp+1], ph, vl + 2);
                mma16816(o[2*dp+1], pl, vh + 2);
            }
        }
    }

    // ---- epilogue ----
    const float ilA = 1.f / lA, ilB = 1.f / lB;
    const int rA = wrow0 + (lane >> 2);
    const int colb = h * HEADD + 2 * (lane & 3);
#pragma unroll
    for (int dt = 0; dt < 16; dt++) {
        *(float2*)(O + (size_t)rA * HDIM + colb + 8 * dt) =
            make_float2(o[dt][0] * ilA, o[dt][1] * ilA);
        *(float2*)(O + (size_t)(rA + 8) * HDIM + colb + 8 * dt) =
            make_float2(o[dt][2] * ilB, o[dt][3] * ilB);
    }
}

// ---------------------------------------------------------------------------
extern "C" void kernel_launch(void* const* d_in, const int* in_sizes, int n_in,
                              void* d_out, int out_size)
{
    const float* x  = (const float*)d_in[0];
    const float* wq = (const float*)d_in[1];
    const float* wk = (const float*)d_in[2];
    const float* wv = (const float*)d_in[3];
    const float* wo = (const float*)d_in[4];
    float* out = (float*)d_out;

    float *qb, *kb, *vb, *ob;
    cudaGetSymbolAddress((void**)&qb, g_q);
    cudaGetSymbolAddress((void**)&kb, g_k);
    cudaGetSymbolAddress((void**)&vb, g_v);
    cudaGetSymbolAddress((void**)&ob, g_o);

    cudaFuncSetAttribute(flash_mma, cudaFuncAttributeMaxDynamicSharedMemorySize, FA2_SMEM);

    // projections (bf16 split-precision tensor-core)
    gemm_bf16s<<<dim3(HDIM / 128,  S_LEN / 128), 256>>>(x, wq, qb, S_LEN, HDIM,  HDIM);
    gemm_bf16s<<<dim3(KVDIM / 128, S_LEN / 128), 256>>>(x, wk, kb, S_LEN, KVDIM, HDIM);
    gemm_bf16s<<<dim3(KVDIM / 128, S_LEN / 128), 256>>>(x, wv, vb, S_LEN, KVDIM, HDIM);

    // RoPE
    rope_table<<<(S_LEN * 64) / 256, 256>>>();
    rope_apply<<<(S_LEN * NHEADS * 64) / 256, 256>>>(qb, NHEADS);
    rope_apply<<<(S_LEN * NKVH * 64) / 256, 256>>>(kb, NKVH);

    // attention (tensor-core flash)
    flash_mma<<<dim3(S_LEN / 128, NHEADS), 256, FA2_SMEM>>>(qb, kb, vb, ob);

    // output projection
    gemm_bf16s<<<dim3(HDIM / 128, S_LEN / 128), 256>>>(ob, wo, out, S_LEN, HDIM, HDIM);
}

// round 7
// speedup vs baseline: 5.1732x; 1.2014x over previous
#include <cuda_runtime.h>
#include <cuda_bf16.h>
#include <cstdint>
#include <math.h>

#define S_LEN 2048
#define HDIM  4096
#define NHEADS 32
#define NKVH   8
#define HEADD  128
#define KVDIM  1024

typedef __nv_bfloat16 bf16;

// ---------------- scratch (static device globals; no allocations) ----------
__device__ float g_q[S_LEN * HDIM];
__device__ float g_k[S_LEN * KVDIM];
__device__ float g_v[S_LEN * KVDIM];
__device__ float g_o[S_LEN * HDIM];
__device__ float g_cos[S_LEN * 64];
__device__ float g_sin[S_LEN * 64];
// bf16 hi/lo panel-major planes (K=4096 -> 128 panels of [R x 32])
__device__ bf16 g_xh[S_LEN * HDIM],  g_xl[S_LEN * HDIM];
__device__ bf16 g_wqh[HDIM * HDIM],  g_wql[HDIM * HDIM];
__device__ bf16 g_wkh[KVDIM * HDIM], g_wkl[KVDIM * HDIM];
__device__ bf16 g_wvh[KVDIM * HDIM], g_wvl[KVDIM * HDIM];
__device__ bf16 g_woh[HDIM * HDIM],  g_wol[HDIM * HDIM];
__device__ bf16 g_oh[S_LEN * HDIM],  g_ol[S_LEN * HDIM];

// ============================================================================
// helpers
// ============================================================================
__device__ __forceinline__ uint32_t smem_u32(const void* p) {
    uint32_t a;
    asm("{ .reg .u64 t; cvta.to.shared.u64 t, %1; cvt.u32.u64 %0, t; }"
        : "=r"(a) : "l"(p));
    return a;
}
__device__ __forceinline__ void ldmx4(uint32_t& r0, uint32_t& r1,
                                      uint32_t& r2, uint32_t& r3, uint32_t addr) {
    asm volatile("ldmatrix.sync.aligned.m8n8.x4.shared.b16 {%0,%1,%2,%3}, [%4];"
                 : "=r"(r0), "=r"(r1), "=r"(r2), "=r"(r3) : "r"(addr));
}
__device__ __forceinline__ void ldmx4t(uint32_t& r0, uint32_t& r1,
                                       uint32_t& r2, uint32_t& r3, uint32_t addr) {
    asm volatile("ldmatrix.sync.aligned.m8n8.x4.trans.shared.b16 {%0,%1,%2,%3}, [%4];"
                 : "=r"(r0), "=r"(r1), "=r"(r2), "=r"(r3) : "r"(addr));
}
__device__ __forceinline__ void mma16816(float* c, const uint32_t* a, const uint32_t* b) {
    asm volatile(
        "mma.sync.aligned.m16n8k16.row.col.f32.bf16.bf16.f32 "
        "{%0,%1,%2,%3}, {%4,%5,%6,%7}, {%8,%9}, {%0,%1,%2,%3};"
        : "+f"(c[0]), "+f"(c[1]), "+f"(c[2]), "+f"(c[3])
        : "r"(a[0]), "r"(a[1]), "r"(a[2]), "r"(a[3]), "r"(b[0]), "r"(b[1]));
}
__device__ __forceinline__ float ex2(float x) {
    float r;
    asm("ex2.approx.ftz.f32 %0, %1;" : "=f"(r) : "f"(x));
    return r;
}
__device__ __forceinline__ void split2(float x, float y, uint32_t& hi, uint32_t& lo) {
    bf16 hx = __float2bfloat16_rn(x);
    bf16 hy = __float2bfloat16_rn(y);
    bf16 lx = __float2bfloat16_rn(x - __bfloat162float(hx));
    bf16 ly = __float2bfloat16_rn(y - __bfloat162float(hy));
    __nv_bfloat162 H = {hx, hy}, L = {lx, ly};
    hi = *reinterpret_cast<uint32_t*>(&H);
    lo = *reinterpret_cast<uint32_t*>(&L);
}

// ============================================================================
// fp32 -> bf16 hi/lo, panel-major: plane[p*R*32 + r*32 + (k&31)], p = k>>5
// ============================================================================
__global__ __launch_bounds__(256) void convert_split(const float* __restrict__ src,
                                                     bf16* __restrict__ H,
                                                     bf16* __restrict__ L, int R)
{
    int idx = blockIdx.x * blockDim.x + threadIdx.x;
    if (idx >= R * 1024) return;
    int r = idx >> 10;
    int k4 = (idx & 1023) * 4;
    float4 v = *(const float4*)(src + (size_t)r * 4096 + k4);
    size_t off = (size_t)(k4 >> 5) * R * 32 + (size_t)r * 32 + (k4 & 31);
    uint32_t h0, l0, h1, l1;
    split2(v.x, v.y, h0, l0);
    split2(v.z, v.w, h1, l1);
    *(uint2*)(H + off) = make_uint2(h0, h1);
    *(uint2*)(L + off) = make_uint2(l0, l1);
}

// ============================================================================
// Pipelined bf16 split GEMM core. BM=BN=128, BK=32 (1 panel/iter), 256 thr.
// Double-buffered smem, stride-80 rows, LDG.128 prefetch, 1 sync/iter.
// ============================================================================
#define PLSZ   10240                 // 128 rows * 80B
#define STAGESZ (4 * PLSZ)           // Ah, Al, Bh, Bl
#define GPIPE_SMEM (2 * STAGESZ)     // 81920

__device__ __forceinline__ void gemm_core(
    const bf16* __restrict__ Ahp, const bf16* __restrict__ Alp, int RA,
    const bf16* __restrict__ Bhp, const bf16* __restrict__ Blp, int RB,
    float* __restrict__ C, int Cs, int m0, int n0, char* sm)
{
    const uint32_t sb = smem_u32(sm);
    const int tid = threadIdx.x, lane = tid & 31, wid = tid >> 5;
    const int wr = wid >> 1, wc = wid & 1;

    // loader: 8 chunks of 16B per thread (2 per plane)
    const bf16* cur[8];
    uint32_t smoff[8];
    size_t pstr[8];
    const bf16* gbase[4] = {Ahp + (size_t)m0 * 32, Alp + (size_t)m0 * 32,
                            Bhp + (size_t)n0 * 32, Blp + (size_t)n0 * 32};
    const size_t pstride[4] = {(size_t)RA * 32, (size_t)RA * 32,
                               (size_t)RB * 32, (size_t)RB * 32};
#pragma unroll
    for (int j = 0; j < 8; j++) {
        int p = j >> 1;
        int cip = tid + 256 * (j & 1);
        cur[j] = gbase[p] + cip * 8;
        pstr[j] = pstride[p];
        smoff[j] = p * PLSZ + (cip >> 2) * 80 + (cip & 3) * 16;
    }

    // frag addresses
    const uint32_t aA = sb + (wr * 32 + (lane & 15)) * 80 + ((lane >> 4) & 1) * 16;
    const uint32_t aB = sb + 2 * PLSZ +
        (wc * 64 + (lane & 7) + ((lane >> 4) & 1) * 8) * 80 + ((lane >> 3) & 1) * 16;

    float acc[2][8][4];
#pragma unroll
    for (int mt = 0; mt < 2; mt++)
#pragma unroll
        for (int nt = 0; nt < 8; nt++)
#pragma unroll
            for (int i = 0; i < 4; i++) acc[mt][nt][i] = 0.f;

    uint4 R[8];
#pragma unroll
    for (int j = 0; j < 8; j++) { R[j] = *(const uint4*)cur[j]; cur[j] += pstr[j]; }

    const int NK = 128;
    for (int it = 0; it < NK; ++it) {
        const uint32_t stg = (uint32_t)(it & 1) * STAGESZ;
        // STS staged chunk
#pragma unroll
        for (int j = 0; j < 8; j++)
            *(uint4*)(sm + stg + smoff[j]) = R[j];
        // prefetch next
        if (it + 1 < NK) {
#pragma unroll
            for (int j = 0; j < 8; j++) { R[j] = *(const uint4*)cur[j]; cur[j] += pstr[j]; }
        }
        __syncthreads();

#pragma unroll
        for (int ks = 0; ks < 2; ks++) {
            const uint32_t ko = stg + ks * 32;
            uint32_t Ah[2][4], Al[2][4], Bh[8][2], Bl[8][2];
#pragma unroll
            for (int mt = 0; mt < 2; mt++) {
                ldmx4(Ah[mt][0], Ah[mt][1], Ah[mt][2], Ah[mt][3],
                      aA + ko + mt * 16 * 80);
                ldmx4(Al[mt][0], Al[mt][1], Al[mt][2], Al[mt][3],
                      aA + ko + PLSZ + mt * 16 * 80);
            }
#pragma unroll
            for (int np = 0; np < 4; np++) {
                ldmx4(Bh[2*np][0], Bh[2*np][1], Bh[2*np+1][0], Bh[2*np+1][1],
                      aB + ko + np * 16 * 80);
                ldmx4(Bl[2*np][0], Bl[2*np][1], Bl[2*np+1][0], Bl[2*np+1][1],
                      aB + ko + PLSZ + np * 16 * 80);
            }
#pragma unroll
            for (int mt = 0; mt < 2; mt++)
#pragma unroll
                for (int nt = 0; nt < 8; nt++) {
                    mma16816(acc[mt][nt], Ah[mt], Bh[nt]);
                    mma16816(acc[mt][nt], Ah[mt], Bl[nt]);
                    mma16816(acc[mt][nt], Al[mt], Bh[nt]);
                }
        }
        // NOTE: no second sync needed — next iter writes the other stage.
    }

    const int gid = lane >> 2, tig = lane & 3;
#pragma unroll
    for (int mt = 0; mt < 2; mt++) {
        const int row = m0 + wr * 32 + mt * 16 + gid;
#pragma unroll
        for (int nt = 0; nt < 8; nt++) {
            const int col = n0 + wc * 64 + nt * 8 + tig * 2;
            *(float2*)(C + (size_t)row * Cs + col) =
                make_float2(acc[mt][nt][0], acc[mt][nt][1]);
            *(float2*)(C + (size_t)(row + 8) * Cs + col) =
                make_float2(acc[mt][nt][2], acc[mt][nt][3]);
        }
    }
}

// fused QKV projection: grid (48, 16)
__global__ __launch_bounds__(256) void gemm_qkv(float* __restrict__ qo,
                                                float* __restrict__ ko,
                                                float* __restrict__ vo)
{
    extern __shared__ char sm[];
    const int bx = blockIdx.x, by = blockIdx.y;
    const bf16 *Bh, *Bl; float* C; int Cs, RB, nb;
    if (bx < 32)      { Bh = g_wqh; Bl = g_wql; C = qo; Cs = 4096; RB = 4096; nb = bx; }
    else if (bx < 40) { Bh = g_wkh; Bl = g_wkl; C = ko; Cs = 1024; RB = 1024; nb = bx - 32; }
    else              { Bh = g_wvh; Bl = g_wvl; C = vo; Cs = 1024; RB = 1024; nb = bx - 40; }
    gemm_core(g_xh, g_xl, 2048, Bh, Bl, RB, C, Cs, by * 128, nb * 128, sm);
}

// output projection: grid (32, 16)
__global__ __launch_bounds__(256) void gemm_wo(float* __restrict__ out)
{
    extern __shared__ char sm[];
    gemm_core(g_oh, g_ol, 2048, g_woh, g_wol, 4096, out, 4096,
              blockIdx.y * 128, blockIdx.x * 128, sm);
}

// ---------------------------------------------------------------------------
// RoPE (unchanged)
// ---------------------------------------------------------------------------
__global__ void rope_table()
{
    int idx = blockIdx.x * blockDim.x + threadIdx.x;
    if (idx >= S_LEN * 64) return;
    int s = idx >> 6, i = idx & 63;
    double inv = pow(500000.0, -(double)i / 64.0);
    double a = (double)s * inv;
    g_cos[idx] = (float)cos(a);
    g_sin[idx] = (float)sin(a);
}
__global__ void rope_apply(float* __restrict__ buf, int nheads)
{
    int idx = blockIdx.x * blockDim.x + threadIdx.x;
    int total = S_LEN * nheads * 64;
    if (idx >= total) return;
    int i = idx & 63;
    int h = (idx >> 6) % nheads;
    int s = idx / (nheads * 64);
    float c  = g_cos[s * 64 + i];
    float sn = g_sin[s * 64 + i];
    float* p = buf + (size_t)s * nheads * HEADD + h * HEADD;
    float x0 = p[i];
    float x1 = p[i + 64];
    p[i]      = x0 * c - x1 * sn;
    p[i + 64] = x1 * c + x0 * sn;
}

// ============================================================================
// Tensor-core flash attention (unchanged from round 4 — validated)
// ============================================================================
#define FRS 272
#define FQH 0
#define FQL (128 * FRS)
#define FKH (2 * 128 * FRS)
#define FKL (FKH + 64 * FRS)
#define FVH (FKH + 2 * 64 * FRS)
#define FVL (FKH + 3 * 64 * FRS)
#define FA2_SMEM (FKH + 4 * 64 * FRS)

__global__ __launch_bounds__(256) void flash_mma(const float* __restrict__ Q,
                                                 const float* __restrict__ K,
                                                 const float* __restrict__ V,
                                                 float* __restrict__ O)
{
    extern __shared__ char sm[];
    const uint32_t sb = smem_u32(sm);
    const int tid = threadIdx.x, lane = tid & 31, wid = tid >> 5;
    const int h = blockIdx.y;
    const int m0 = blockIdx.x * 128;
    const int kvh = h >> 2;
    const float qscale = 0.0883883476483184f * 1.4426950408889634f;

    {
        int row = tid >> 1, half = tid & 1;
        const float* qp = Q + (size_t)(m0 + row) * HDIM + h * HEADD + half * 64;
        char* dh = sm + FQH + row * FRS + half * 128;
        char* dl = sm + FQL + row * FRS + half * 128;
#pragma unroll
        for (int c = 0; c < 16; c++) {
            float4 v = ((const float4*)qp)[c];
            v.x *= qscale; v.y *= qscale; v.z *= qscale; v.w *= qscale;
            uint32_t h0, l0, h1, l1;
            split2(v.x, v.y, h0, l0);
            split2(v.z, v.w, h1, l1);
            ((uint2*)dh)[c] = make_uint2(h0, h1);
            ((uint2*)dl)[c] = make_uint2(l0, l1);
        }
    }

    float o[16][4];
#pragma unroll
    for (int dt = 0; dt < 16; dt++)
#pragma unroll
        for (int i = 0; i < 4; i++) o[dt][i] = 0.f;
    float mA = -1e30f, mB = -1e30f, lA = 0.f, lB = 0.f;

    const int wrow0 = m0 + wid * 16;
    const uint32_t aQh = sb + FQH + (wid * 16 + (lane & 15)) * FRS + ((lane >> 4) & 1) * 16;
    const uint32_t aQl = aQh + (FQL - FQH);
    const uint32_t kRow = (uint32_t)((lane & 7) + ((lane >> 4) & 1) * 8);
    const uint32_t kKo  = (uint32_t)(((lane >> 3) & 1) * 16);
    const uint32_t aKh = sb + FKH + kRow * FRS + kKo;
    const uint32_t aKl = aKh + (FKL - FKH);
    const uint32_t vRow = (uint32_t)((lane & 7) + ((lane >> 3) & 1) * 8);
    const uint32_t vDo  = (uint32_t)(((lane >> 4) & 1) * 16);
    const uint32_t aVh = sb + FVH + vRow * FRS + vDo;
    const uint32_t aVl = aVh + (FVL - FVH);

    const int jmax = 2 * blockIdx.x + 1;
    for (int j = 0; j <= jmax; j++) {
        const int n0 = j * 64;
        __syncthreads();
        {
            int row = tid >> 2, q = tid & 3;
            const float* kp = K + (size_t)(n0 + row) * KVDIM + kvh * HEADD + q * 32;
            const float* vp = V + (size_t)(n0 + row) * KVDIM + kvh * HEADD + q * 32;
            char* kh = sm + FKH + row * FRS + q * 64;
            char* kl = sm + FKL + row * FRS + q * 64;
            char* vh = sm + FVH + row * FRS + q * 64;
            char* vl = sm + FVL + row * FRS + q * 64;
#pragma unroll
            for (int c = 0; c < 8; c++) {
                float4 x = ((const float4*)kp)[c];
                uint32_t h0, l0, h1, l1;
                split2(x.x, x.y, h0, l0);
                split2(x.z, x.w, h1, l1);
                ((uint2*)kh)[c] = make_uint2(h0, h1);
                ((uint2*)kl)[c] = make_uint2(l0, l1);
                x = ((const float4*)vp)[c];
                split2(x.x, x.y, h0, l0);
                split2(x.z, x.w, h1, l1);
                ((uint2*)vh)[c] = make_uint2(h0, h1);
                ((uint2*)vl)[c] = make_uint2(l0, l1);
            }
        }
        __syncthreads();

        if (n0 > wrow0 + 15) continue;

        float s[8][4];
#pragma unroll
        for (int t = 0; t < 8; t++)
#pragma unroll
            for (int i = 0; i < 4; i++) s[t][i] = 0.f;

#pragma unroll
        for (int kc = 0; kc < 8; kc++) {
            uint32_t qh[4], ql[4];
            ldmx4(qh[0], qh[1], qh[2], qh[3], aQh + kc * 32);
            ldmx4(ql[0], ql[1], ql[2], ql[3], aQl + kc * 32);
#pragma unroll
            for (int np = 0; np < 4; np++) {
                uint32_t kh[4], kl[4];
                ldmx4(kh[0], kh[1], kh[2], kh[3], aKh + np * 16 * FRS + kc * 32);
                ldmx4(kl[0], kl[1], kl[2], kl[3], aKl + np * 16 * FRS + kc * 32);
                mma16816(s[2*np],   qh, kh);
                mma16816(s[2*np],   qh, kl);
                mma16816(s[2*np],   ql, kh);
                mma16816(s[2*np+1], qh, kh + 2);
                mma16816(s[2*np+1], qh, kl + 2);
                mma16816(s[2*np+1], ql, kh + 2);
            }
        }

        const int rA = wrow0 + (lane >> 2);
        const int rB = rA + 8;
        const int cb = n0 + 2 * (lane & 3);
        if (n0 + 63 > wrow0) {
#pragma unroll
            for (int t = 0; t < 8; t++) {
                int c0 = cb + 8 * t;
                if (c0     > rA) s[t][0] = -1e30f;
                if (c0 + 1 > rA) s[t][1] = -1e30f;
                if (c0     > rB) s[t][2] = -1e30f;
                if (c0 + 1 > rB) s[t][3] = -1e30f;
            }
        }

        float xA = -1e30f, xB = -1e30f;
#pragma unroll
        for (int t = 0; t < 8; t++) {
            xA = fmaxf(xA, fmaxf(s[t][0], s[t][1]));
            xB = fmaxf(xB, fmaxf(s[t][2], s[t][3]));
        }
        xA = fmaxf(xA, __shfl_xor_sync(0xffffffffu, xA, 1));
        xA = fmaxf(xA, __shfl_xor_sync(0xffffffffu, xA, 2));
        xB = fmaxf(xB, __shfl_xor_sync(0xffffffffu, xB, 1));
        xB = fmaxf(xB, __shfl_xor_sync(0xffffffffu, xB, 2));
        float mAn = fmaxf(mA, xA), mBn = fmaxf(mB, xB);
        float cA = ex2(mA - mAn), cB = ex2(mB - mBn);
        mA = mAn; mB = mBn;
        float sumA = 0.f, sumB = 0.f;
#pragma unroll
        for (int t = 0; t < 8; t++) {
            s[t][0] = ex2(s[t][0] - mA); sumA += s[t][0];
            s[t][1] = ex2(s[t][1] - mA); sumA += s[t][1];
            s[t][2] = ex2(s[t][2] - mB); sumB += s[t][2];
            s[t][3] = ex2(s[t][3] - mB); sumB += s[t][3];
        }
        sumA += __shfl_xor_sync(0xffffffffu, sumA, 1);
        sumA += __shfl_xor_sync(0xffffffffu, sumA, 2);
        sumB += __shfl_xor_sync(0xffffffffu, sumB, 1);
        sumB += __shfl_xor_sync(0xffffffffu, sumB, 2);
        lA = lA * cA + sumA;
        lB = lB * cB + sumB;
#pragma unroll
        for (int dt = 0; dt < 16; dt++) {
            o[dt][0] *= cA; o[dt][1] *= cA;
            o[dt][2] *= cB; o[dt][3] *= cB;
        }

#pragma unroll
        for (int kc = 0; kc < 4; kc++) {
            uint32_t ph[4], pl[4];
            split2(s[2*kc][0],   s[2*kc][1],   ph[0], pl[0]);
            split2(s[2*kc][2],   s[2*kc][3],   ph[1], pl[1]);
            split2(s[2*kc+1][0], s[2*kc+1][1], ph[2], pl[2]);
            split2(s[2*kc+1][2], s[2*kc+1][3], ph[3], pl[3]);
#pragma unroll
            for (int dp = 0; dp < 8; dp++) {
                uint32_t vh[4], vl[4];
                ldmx4t(vh[0], vh[1], vh[2], vh[3], aVh + kc * 16 * FRS + dp * 32);
                ldmx4t(vl[0], vl[1], vl[2], vl[3], aVl + kc * 16 * FRS + dp * 32);
                mma16816(o[2*dp],   ph, vh);
                mma16816(o[2*dp],   ph, vl);
                mma16816(o[2*dp],   pl, vh);
                mma16816(o[2*dp+1], ph, vh + 2);
                mma16816(o[2*dp+1], ph, vl + 2);
                mma16816(o[2*dp+1], pl, vh + 2);
            }
        }
    }

    const float ilA = 1.f / lA, ilB = 1.f / lB;
    const int rA = wrow0 + (lane >> 2);
    const int colb = h * HEADD + 2 * (lane & 3);
#pragma unroll
    for (int dt = 0; dt < 16; dt++) {
        *(float2*)(O + (size_t)rA * HDIM + colb + 8 * dt) =
            make_float2(o[dt][0] * ilA, o[dt][1] * ilA);
        *(float2*)(O + (size_t)(rA + 8) * HDIM + colb + 8 * dt) =
            make_float2(o[dt][2] * ilB, o[dt][3] * ilB);
    }
}

// ---------------------------------------------------------------------------
extern "C" void kernel_launch(void* const* d_in, const int* in_sizes, int n_in,
                              void* d_out, int out_size)
{
    const float* x  = (const float*)d_in[0];
    const float* wq = (const float*)d_in[1];
    const float* wk = (const float*)d_in[2];
    const float* wv = (const float*)d_in[3];
    const float* wo = (const float*)d_in[4];
    float* out = (float*)d_out;

    float *qb, *kb, *vb, *ob;
    cudaGetSymbolAddress((void**)&qb, g_q);
    cudaGetSymbolAddress((void**)&kb, g_k);
    cudaGetSymbolAddress((void**)&vb, g_v);
    cudaGetSymbolAddress((void**)&ob, g_o);
    bf16 *xh, *xl, *wqh, *wql, *wkh, *wkl, *wvh, *wvl, *woh, *wol, *oh, *ol;
    cudaGetSymbolAddress((void**)&xh,  g_xh);  cudaGetSymbolAddress((void**)&xl,  g_xl);
    cudaGetSymbolAddress((void**)&wqh, g_wqh); cudaGetSymbolAddress((void**)&wql, g_wql);
    cudaGetSymbolAddress((void**)&wkh, g_wkh); cudaGetSymbolAddress((void**)&wkl, g_wkl);
    cudaGetSymbolAddress((void**)&wvh, g_wvh); cudaGetSymbolAddress((void**)&wvl, g_wvl);
    cudaGetSymbolAddress((void**)&woh, g_woh); cudaGetSymbolAddress((void**)&wol, g_wol);
    cudaGetSymbolAddress((void**)&oh,  g_oh);  cudaGetSymbolAddress((void**)&ol,  g_ol);

    cudaFuncSetAttribute(flash_mma, cudaFuncAttributeMaxDynamicSharedMemorySize, FA2_SMEM);
    cudaFuncSetAttribute(gemm_qkv,  cudaFuncAttributeMaxDynamicSharedMemorySize, GPIPE_SMEM);
    cudaFuncSetAttribute(gemm_wo,   cudaFuncAttributeMaxDynamicSharedMemorySize, GPIPE_SMEM);

    // preconvert inputs/weights to panel-major bf16 hi/lo
    convert_split<<<(2048 * 1024) / 256, 256>>>(x,  xh,  xl,  2048);
    convert_split<<<(4096 * 1024) / 256, 256>>>(wq, wqh, wql, 4096);
    convert_split<<<(1024 * 1024) / 256, 256>>>(wk, wkh, wkl, 1024);
    convert_split<<<(1024 * 1024) / 256, 256>>>(wv, wvh, wvl, 1024);
    convert_split<<<(4096 * 1024) / 256, 256>>>(wo, woh, wol, 4096);

    // fused QKV projection
    gemm_qkv<<<dim3(48, 16), 256, GPIPE_SMEM>>>(qb, kb, vb);

    // RoPE
    rope_table<<<(S_LEN * 64) / 256, 256>>>();
    rope_apply<<<(S_LEN * NHEADS * 64) / 256, 256>>>(qb, NHEADS);
    rope_apply<<<(S_LEN * NKVH * 64) / 256, 256>>>(kb, NKVH);

    // attention
    flash_mma<<<dim3(S_LEN / 128, NHEADS), 256, FA2_SMEM>>>(qb, kb, vb, ob);

    // convert attention output, then output projection
    convert_split<<<(2048 * 1024) / 256, 256>>>(ob, oh, ol, 2048);
    gemm_wo<<<dim3(32, 16), 256, GPIPE_SMEM>>>(out);
}